// round 10
// baseline (speedup 1.0000x reference)
#include <cuda_runtime.h>
#include <math_constants.h>

#define CC 192
#define KK 64
#define NBINS 2048
#define BIN_LO (-10.5f)
#define BIN_W  (21.0f / (float)NBINS)
#define BIN_INV ((float)NBINS / 21.0f)
#define LIK_BOUND 1e-9f

// {y, lik} per (channel, code)
__device__ float2 g_tab[CC * KK];
// midpoints (63 real + 1 INF sentinel)
__device__ float g_mid[KK];
// per-bin: low byte = k0 (count with 2-bin slack), bit8 = dirty flag
__device__ unsigned short g_bin[NBINS];

__device__ __forceinline__ float softplusf(float x) {
    return fmaxf(x, 0.0f) + log1pf(expf(-fabsf(x)));
}

__device__ __forceinline__ int count_mids_below(const float* __restrict__ cb, float v) {
    int lo = 0, hi = KK - 1;   // lower_bound over 63 midpoints
    while (lo < hi) {
        int m = (lo + hi) >> 1;
        float mid = 0.5f * (cb[m] + cb[m + 1]);
        if (mid < v) lo = m + 1; else hi = m;
    }
    return lo;
}

// grid = 200 blocks x 128 threads.
// blocks [0,192): one channel each; tid<64 -> lower eval, tid>=64 -> upper eval.
// blocks [192,200): bin table (256 bins each) + midpoints (block 192).
__global__ void __launch_bounds__(128) build_lut_kernel(
    const float* __restrict__ cb,
    const float* __restrict__ m0, const float* __restrict__ m1,
    const float* __restrict__ m2, const float* __restrict__ m3,
    const float* __restrict__ m4,
    const float* __restrict__ b0, const float* __restrict__ b1,
    const float* __restrict__ b2, const float* __restrict__ b3,
    const float* __restrict__ b4,
    const float* __restrict__ f0, const float* __restrict__ f1,
    const float* __restrict__ f2, const float* __restrict__ f3)
{
    int tid = threadIdx.x;
    int blk = blockIdx.x;

    if (blk >= CC) {
        // ---- bin table + midpoints ----
        int bb = blk - CC;
        if (bb == 0 && tid < KK) {
            g_mid[tid] = (tid < KK - 1) ? 0.5f * (cb[tid] + cb[tid + 1]) : CUDART_INF_F;
        }
        #pragma unroll
        for (int r = 0; r < 2; r++) {
            int t = bb * 256 + r * 128 + tid;
            float wlo = BIN_LO + (float)(t - 2) * BIN_W;
            float whi = BIN_LO + (float)(t + 3) * BIN_W;
            int k0  = count_mids_below(cb, wlo);
            int khi = count_mids_below(cb, whi);
            unsigned short e = (unsigned short)k0;
            if (khi > k0) e |= 0x100;   // dirty: midpoint(s) inside safety window
            g_bin[t] = e;
        }
    } else {
        int c = blk;
        int s = tid >> 6;      // 0 = lower, 1 = upper
        int k = tid & 63;

        float w0[3], w4[3], bb0[3], bb1[3], bb2[3], bb3[3], bb4;
        float t0[3], t1[3], t2[3], t3[3];
        float w1[9], w2[9], w3[9];
        #pragma unroll
        for (int j = 0; j < 3; j++) {
            w0[j]  = softplusf(m0[c * 3 + j]);
            w4[j]  = softplusf(m4[c * 3 + j]);
            bb0[j] = b0[c * 3 + j];
            bb1[j] = b1[c * 3 + j];
            bb2[j] = b2[c * 3 + j];
            bb3[j] = b3[c * 3 + j];
            t0[j]  = tanhf(f0[c * 3 + j]);
            t1[j]  = tanhf(f1[c * 3 + j]);
            t2[j]  = tanhf(f2[c * 3 + j]);
            t3[j]  = tanhf(f3[c * 3 + j]);
        }
        #pragma unroll
        for (int j = 0; j < 9; j++) {
            w1[j] = softplusf(m1[c * 9 + j]);
            w2[j] = softplusf(m2[c * 9 + j]);
            w3[j] = softplusf(m3[c * 9 + j]);
        }
        bb4 = b4[c];

        float u = cb[k] + (s ? 0.5f : -0.5f);
        float h[3], nt[3];
        #pragma unroll
        for (int j = 0; j < 3; j++) {
            h[j] = w0[j] * u + bb0[j];
            h[j] += t0[j] * tanhf(h[j]);
        }
        #pragma unroll
        for (int j = 0; j < 3; j++) {
            nt[j] = w1[j*3+0]*h[0] + w1[j*3+1]*h[1] + w1[j*3+2]*h[2] + bb1[j];
            nt[j] += t1[j] * tanhf(nt[j]);
        }
        #pragma unroll
        for (int j = 0; j < 3; j++) h[j] = nt[j];
        #pragma unroll
        for (int j = 0; j < 3; j++) {
            nt[j] = w2[j*3+0]*h[0] + w2[j*3+1]*h[1] + w2[j*3+2]*h[2] + bb2[j];
            nt[j] += t2[j] * tanhf(nt[j]);
        }
        #pragma unroll
        for (int j = 0; j < 3; j++) h[j] = nt[j];
        #pragma unroll
        for (int j = 0; j < 3; j++) {
            nt[j] = w3[j*3+0]*h[0] + w3[j*3+1]*h[1] + w3[j*3+2]*h[2] + bb3[j];
            nt[j] += t3[j] * tanhf(nt[j]);
        }
        #pragma unroll
        for (int j = 0; j < 3; j++) h[j] = nt[j];
        float out = w4[0]*h[0] + w4[1]*h[1] + w4[2]*h[2] + bb4;

        __shared__ float souts[2][KK];
        souts[s][k] = out;
        __syncthreads();

        if (tid < KK) {
            float lo = souts[0][tid], up = souts[1][tid];
            float ssum = lo + up;
            float sg = (ssum > 0.0f) ? -1.0f : ((ssum < 0.0f) ? 1.0f : 0.0f);
            float su = 1.0f / (1.0f + expf(-sg * up));
            float sl = 1.0f / (1.0f + expf(-sg * lo));
            float lik = fmaxf(fabsf(su - sl), LIK_BOUND);
            g_tab[c * KK + tid] = make_float2(cb[tid], lik);
        }
    }

    // PDL: allow the dependent (quant) kernel to begin
    asm volatile("griddepcontrol.launch_dependents;");
}

// Each block = 256 threads x 4 float4 = 4096 elements = exactly one (n,c) plane.
__global__ void __launch_bounds__(256) quant_lik_kernel(
    const float4* __restrict__ x4,
    float4* __restrict__ y4,
    float4* __restrict__ l4)
{
    __shared__ float2 stab[KK];
    __shared__ float  smid[KK];
    __shared__ unsigned short sbin[NBINS];

    int tid = threadIdx.x;
    int c = blockIdx.x % CC;

    long base = (long)blockIdx.x * 1024 + tid;  // float4 units; stride 256

    // Prefetch all x for this thread BEFORE waiting on the producer (PDL overlap)
    float4 xv[4];
    #pragma unroll
    for (int v = 0; v < 4; v++) xv[v] = x4[base + v * 256];

    asm volatile("griddepcontrol.wait;" ::: "memory");

    if (tid < KK) {
        stab[tid] = g_tab[c * KK + tid];
        smid[tid] = g_mid[tid];
    }
    // 2048 u16 = 4KB: one int4 per thread
    ((int4*)sbin)[tid] = ((const int4*)g_bin)[tid];
    __syncthreads();

    #pragma unroll
    for (int v = 0; v < 4; v++) {
        float4 q = xv[v];
        float xs[4] = {q.x, q.y, q.z, q.w};
        float ys[4], ls[4];

        #pragma unroll
        for (int j = 0; j < 4; j++) {
            float xx = xs[j];
            int bin = __float2int_rd((xx - BIN_LO) * BIN_INV);
            bin = min(max(bin, 0), NBINS - 1);
            unsigned e = sbin[bin];
            int k = (int)(e & 0xFFu);
            if (e & 0x100u) {
                k += (smid[k] < xx);
                k += (smid[k] < xx);
                k += (smid[k] < xx);
                while (smid[k] < xx) k++;   // smid[63] = +INF bounds
            }
            float2 yl = stab[k];
            ys[j] = yl.x;
            ls[j] = yl.y;
        }

        long i = base + v * 256;
        y4[i] = make_float4(ys[0], ys[1], ys[2], ys[3]);
        l4[i] = make_float4(ls[0], ls[1], ls[2], ls[3]);
    }
}

extern "C" void kernel_launch(void* const* d_in, const int* in_sizes, int n_in,
                              void* d_out, int out_size)
{
    // metadata order: x, codebook, m0, b0, f0, m1, b1, f1, m2, b2, f2, m3, b3, f3, m4, b4
    const float* x  = (const float*)d_in[0];
    const float* cb = (const float*)d_in[1];
    const float* m0 = (const float*)d_in[2];
    const float* b0 = (const float*)d_in[3];
    const float* f0 = (const float*)d_in[4];
    const float* m1 = (const float*)d_in[5];
    const float* b1 = (const float*)d_in[6];
    const float* f1 = (const float*)d_in[7];
    const float* m2 = (const float*)d_in[8];
    const float* b2 = (const float*)d_in[9];
    const float* f2 = (const float*)d_in[10];
    const float* m3 = (const float*)d_in[11];
    const float* b3 = (const float*)d_in[12];
    const float* f3 = (const float*)d_in[13];
    const float* m4 = (const float*)d_in[14];
    const float* b4 = (const float*)d_in[15];

    long total = (long)in_sizes[0];        // 16*192*64*64 = 12582912
    int nblocks = (int)(total / 4096);     // one (n,c) plane per block = 3072

    float* yhat = (float*)d_out;
    float* lik  = (float*)d_out + total;

    build_lut_kernel<<<CC + NBINS / 256, 128>>>(
        cb, m0, m1, m2, m3, m4, b0, b1, b2, b3, b4, f0, f1, f2, f3);

    // Launch quant with Programmatic Stream Serialization (PDL overlap)
    cudaLaunchConfig_t cfg = {};
    cfg.gridDim = dim3((unsigned)nblocks);
    cfg.blockDim = dim3(256);
    cfg.dynamicSmemBytes = 0;
    cfg.stream = 0;
    cudaLaunchAttribute attrs[1];
    attrs[0].id = cudaLaunchAttributeProgrammaticStreamSerialization;
    attrs[0].val.programmaticStreamSerializationAllowed = 1;
    cfg.attrs = attrs;
    cfg.numAttrs = 1;
    cudaLaunchKernelEx(&cfg, quant_lik_kernel,
                       (const float4*)x, (float4*)yhat, (float4*)lik);
}

// round 11
// speedup vs baseline: 1.4117x; 1.4117x over previous
#include <cuda_runtime.h>
#include <math_constants.h>

#define CC 192
#define KK 64
#define NBINS 2048
#define BIN_LO (-10.5f)
#define BIN_W  (21.0f / (float)NBINS)
#define BIN_INV ((float)NBINS / 21.0f)
#define LIK_BOUND 1e-9f
#define PGROUPS 4                 // blocks per channel
#define PPB (16 / PGROUPS)        // planes per block = 4

__device__ __forceinline__ float softplusf(float x) {
    return fmaxf(x, 0.0f) + log1pf(expf(-fabsf(x)));
}

// grid = CC * PGROUPS = 768 blocks, 256 threads.
// Block b: channel c = b % CC, planes n = (b/CC)*PPB .. +PPB-1.
// Fully self-sufficient: builds its channel LUT + bin table in-block, then streams.
__global__ void __launch_bounds__(256, 6) fused_quant_lik_kernel(
    const float4* __restrict__ x4,
    const float*  __restrict__ cb,
    const float* __restrict__ m0, const float* __restrict__ b0, const float* __restrict__ f0,
    const float* __restrict__ m1, const float* __restrict__ b1, const float* __restrict__ f1,
    const float* __restrict__ m2, const float* __restrict__ b2, const float* __restrict__ f2,
    const float* __restrict__ m3, const float* __restrict__ b3, const float* __restrict__ f3,
    const float* __restrict__ m4, const float* __restrict__ b4,
    float4* __restrict__ y4,
    float4* __restrict__ l4)
{
    __shared__ float2 stab[KK];
    __shared__ float  smid[KK];
    __shared__ unsigned short sbin[NBINS];
    __shared__ float  souts[2][KK];

    int tid = threadIdx.x;
    int c  = blockIdx.x % CC;
    int pg = blockIdx.x / CC;

    // L2 prefetch of the first two planes (no register cost; overlaps setup)
    {
        const float* xp = (const float*)x4;
        #pragma unroll
        for (int p = 0; p < 2; p++) {
            long e = (((long)(pg * PPB + p) * CC + c) * 1024 + tid) * 4;
            #pragma unroll
            for (int v = 0; v < 4; v++) {
                asm volatile("prefetch.global.L2 [%0];" :: "l"(xp + e + v * 1024) : "memory");
            }
        }
    }

    // ---- midpoints (63 real + INF sentinel) ----
    if (tid < KK) {
        smid[tid] = (tid < KK - 1) ? 0.5f * (cb[tid] + cb[tid + 1]) : CUDART_INF_F;
    }
    __syncthreads();

    if (tid < 128) {
        // ---- channel LUT: tid<64 -> lower eval, tid>=64 -> upper eval ----
        int s = tid >> 6;
        int k = tid & 63;

        float w0[3], w4[3], bb0[3], bb1[3], bb2[3], bb3[3], bb4;
        float t0[3], t1[3], t2[3], t3[3];
        float w1[9], w2[9], w3[9];
        #pragma unroll
        for (int j = 0; j < 3; j++) {
            w0[j]  = softplusf(m0[c * 3 + j]);
            w4[j]  = softplusf(m4[c * 3 + j]);
            bb0[j] = b0[c * 3 + j];
            bb1[j] = b1[c * 3 + j];
            bb2[j] = b2[c * 3 + j];
            bb3[j] = b3[c * 3 + j];
            t0[j]  = tanhf(f0[c * 3 + j]);
            t1[j]  = tanhf(f1[c * 3 + j]);
            t2[j]  = tanhf(f2[c * 3 + j]);
            t3[j]  = tanhf(f3[c * 3 + j]);
        }
        #pragma unroll
        for (int j = 0; j < 9; j++) {
            w1[j] = softplusf(m1[c * 9 + j]);
            w2[j] = softplusf(m2[c * 9 + j]);
            w3[j] = softplusf(m3[c * 9 + j]);
        }
        bb4 = b4[c];

        float u = cb[k] + (s ? 0.5f : -0.5f);
        float h[3], nt[3];
        #pragma unroll
        for (int j = 0; j < 3; j++) {
            h[j] = w0[j] * u + bb0[j];
            h[j] += t0[j] * tanhf(h[j]);
        }
        #pragma unroll
        for (int j = 0; j < 3; j++) {
            nt[j] = w1[j*3+0]*h[0] + w1[j*3+1]*h[1] + w1[j*3+2]*h[2] + bb1[j];
            nt[j] += t1[j] * tanhf(nt[j]);
        }
        #pragma unroll
        for (int j = 0; j < 3; j++) h[j] = nt[j];
        #pragma unroll
        for (int j = 0; j < 3; j++) {
            nt[j] = w2[j*3+0]*h[0] + w2[j*3+1]*h[1] + w2[j*3+2]*h[2] + bb2[j];
            nt[j] += t2[j] * tanhf(nt[j]);
        }
        #pragma unroll
        for (int j = 0; j < 3; j++) h[j] = nt[j];
        #pragma unroll
        for (int j = 0; j < 3; j++) {
            nt[j] = w3[j*3+0]*h[0] + w3[j*3+1]*h[1] + w3[j*3+2]*h[2] + bb3[j];
            nt[j] += t3[j] * tanhf(nt[j]);
        }
        #pragma unroll
        for (int j = 0; j < 3; j++) h[j] = nt[j];
        souts[s][k] = w4[0]*h[0] + w4[1]*h[1] + w4[2]*h[2] + bb4;
    } else {
        // ---- bin table: 16 consecutive bins per thread (threads 128..255) ----
        // Same semantics as R5 builder: k0[t] = #mids < binLeft(t-2),
        // dirty if #mids < binLeft(t+3) > k0. Monotone two-pointer advance.
        int T = (tid - 128) * 16;
        float v0 = BIN_LO + (float)(T - 2) * BIN_W;
        // lower_bound over 63 midpoints: first idx with smid[idx] >= v0
        int k = 0;
        {
            int lo = 0, hi = KK - 1;
            while (lo < hi) {
                int m = (lo + hi) >> 1;
                if (smid[m] < v0) lo = m + 1; else hi = m;
            }
            k = lo;
        }
        int kh = k;
        #pragma unroll 4
        for (int t = T; t < T + 16; t++) {
            float wlo = BIN_LO + (float)(t - 2) * BIN_W;
            float whi = BIN_LO + (float)(t + 3) * BIN_W;
            while (smid[k]  < wlo) k++;    // smid[63] = +INF bounds
            while (smid[kh] < whi) kh++;
            sbin[t] = (unsigned short)(k | ((kh > k) ? 0x100 : 0));
        }
    }
    __syncthreads();

    if (tid < KK) {
        float lo = souts[0][tid], up = souts[1][tid];
        float ssum = lo + up;
        float sg = (ssum > 0.0f) ? -1.0f : ((ssum < 0.0f) ? 1.0f : 0.0f);
        float su = 1.0f / (1.0f + expf(-sg * up));
        float sl = 1.0f / (1.0f + expf(-sg * lo));
        float lik = fmaxf(fabsf(su - sl), LIK_BOUND);
        stab[tid] = make_float2(cb[tid], lik);
    }
    __syncthreads();

    // ---- mainloop: R5's proven body, 4 planes ----
    #pragma unroll
    for (int p = 0; p < PPB; p++) {
        long pbase = ((long)(pg * PPB + p) * CC + c) * 1024 + tid;  // float4 units

        float4 xv[4];
        #pragma unroll
        for (int v = 0; v < 4; v++) xv[v] = x4[pbase + v * 256];

        #pragma unroll
        for (int v = 0; v < 4; v++) {
            float4 q = xv[v];
            float xs[4] = {q.x, q.y, q.z, q.w};
            float ys[4], ls[4];

            #pragma unroll
            for (int j = 0; j < 4; j++) {
                float xx = xs[j];
                int bin = __float2int_rd((xx - BIN_LO) * BIN_INV);
                bin = min(max(bin, 0), NBINS - 1);
                unsigned e = sbin[bin];
                int k = (int)(e & 0xFFu);
                if (e & 0x100u) {
                    k += (smid[k] < xx);
                    k += (smid[k] < xx);
                    k += (smid[k] < xx);
                    while (smid[k] < xx) k++;   // smid[63] = +INF bounds
                }
                float2 yl = stab[k];
                ys[j] = yl.x;
                ls[j] = yl.y;
            }

            long i = pbase + v * 256;
            y4[i] = make_float4(ys[0], ys[1], ys[2], ys[3]);
            l4[i] = make_float4(ls[0], ls[1], ls[2], ls[3]);
        }
    }
}

extern "C" void kernel_launch(void* const* d_in, const int* in_sizes, int n_in,
                              void* d_out, int out_size)
{
    // metadata order: x, codebook, m0, b0, f0, m1, b1, f1, m2, b2, f2, m3, b3, f3, m4, b4
    const float* x  = (const float*)d_in[0];
    const float* cb = (const float*)d_in[1];
    const float* m0 = (const float*)d_in[2];
    const float* b0 = (const float*)d_in[3];
    const float* f0 = (const float*)d_in[4];
    const float* m1 = (const float*)d_in[5];
    const float* b1 = (const float*)d_in[6];
    const float* f1 = (const float*)d_in[7];
    const float* m2 = (const float*)d_in[8];
    const float* b2 = (const float*)d_in[9];
    const float* f2 = (const float*)d_in[10];
    const float* m3 = (const float*)d_in[11];
    const float* b3 = (const float*)d_in[12];
    const float* f3 = (const float*)d_in[13];
    const float* m4 = (const float*)d_in[14];
    const float* b4 = (const float*)d_in[15];

    long total = (long)in_sizes[0];        // 16*192*64*64 = 12582912

    float* yhat = (float*)d_out;
    float* lik  = (float*)d_out + total;

    fused_quant_lik_kernel<<<CC * PGROUPS, 256>>>(
        (const float4*)x, cb,
        m0, b0, f0, m1, b1, f1, m2, b2, f2, m3, b3, f3, m4, b4,
        (float4*)yhat, (float4*)lik);
}